// round 12
// baseline (speedup 1.0000x reference)
#include <cuda_runtime.h>

// NCC: per-(b,c) 21x21 normalized cross-correlation, fp32.
// R12 = R10 (best, 254.1us: pipeline + parity-split FMA order) with the
// epilogue overhead reclaimed:
//   - sqrt.approx + rcp.approx (2 MUFU/output vs IEEE div+sqrt sequences;
//     ~2^-23 rel err, tolerance is 1e-3)
//   - tree-structured 21-tap initial box sums (84-cyc serial chain -> ~20)
//   - early acc->num reduction (frees 16 regs before epilogue peak)
//   - compact V rows (608B)
// Mainloop untouched (measured plateau: 59-61% fma across occ 12/24/36%).

#define EPSF    1e-8f
#define TH      21
#define PLANES  48
#define H       512
#define W       512
#define OH      492
#define OW      492
#define NPAIR   11
#define TILE_X  128          // 8 x-threads * 16 outputs
#define TILE_Y  32           // 32 y-threads * 1 row
#define SROWS   (TILE_Y + 20)     // 52
#define NCHUNK  37                // 148 floats = 37 16B-chunks (logical)
#define ROWCH   40                // padded physical chunks per row
#define ROWB    (ROWCH * 16)      // 640 B row stride
#define VROWB   608               // compact V row stride
#define NTHREADS 256

typedef unsigned long long ull;

// interleaved packed weight table: [plane][filter_row][pair] = (wE, wO)
__device__ ulonglong2 g_wEO[PLANES * TH * NPAIR];

__device__ __forceinline__ ull pack2(float a, float b) {
    ull r; asm("mov.b64 %0, {%1,%2};" : "=l"(r) : "f"(a), "f"(b)); return r;
}
__device__ __forceinline__ float lo2(ull v) { return __int_as_float((int)(v & 0xffffffffull)); }
__device__ __forceinline__ float hi2(ull v) { return __int_as_float((int)(v >> 32)); }

// volatile: keep issue order so consecutive FMA2s share the b-operand slot
#define FMA2V(acc, a, b) \
    asm volatile("fma.rn.f32x2 %0, %1, %2, %0;" : "+l"(acc) : "l"(a), "l"(b))

__device__ __forceinline__ float sqrt_approx(float x) {
    float r; asm("sqrt.approx.f32 %0, %1;" : "=f"(r) : "f"(x)); return r;
}
__device__ __forceinline__ float rcp_approx(float x) {
    float r; asm("rcp.approx.f32 %0, %1;" : "=f"(r) : "f"(x)); return r;
}

// XOR swizzle on 16B-chunk index (keeps chunks inside their 128B segment)
__device__ __forceinline__ int swz(int c) { return c ^ ((c >> 3) & 7); }

// smem layout (bytes)
#define OFF_W    0
#define SZ_W     (TH * NPAIR * 16)            // 3696
#define OFF_IN   3712                          // 16B aligned
#define SZ_IN    (SROWS * ROWB)                // 33280
#define OFF_V1   (OFF_IN + SZ_IN)              // 36992
#define SZ_V     (TILE_Y * VROWB)              // 19456
#define OFF_V2   (OFF_V1 + SZ_V)               // 56448
#define SMEM_TOTAL (OFF_V2 + SZ_V)             // 75904

// ---------------------------------------------------------------------------
// Pass 0: normalize template planes, build interleaved packed weight table.
// ---------------------------------------------------------------------------
__global__ void prep_template(const float* __restrict__ tmpl) {
    const int plane = blockIdx.x;
    const float* t = tmpl + plane * (TH * TH);

    __shared__ float s_t[TH * TH];
    __shared__ float s_sa[8], s_sb[8];
    __shared__ float s_mean, s_inv;

    int tid = threadIdx.x;
    float a = 0.f, b = 0.f;
    for (int i = tid; i < TH * TH; i += NTHREADS) {
        float v = t[i];
        s_t[i] = v;
        a += v; b += v * v;
    }
    #pragma unroll
    for (int o = 16; o; o >>= 1) {
        a += __shfl_xor_sync(0xffffffffu, a, o);
        b += __shfl_xor_sync(0xffffffffu, b, o);
    }
    if ((tid & 31) == 0) { s_sa[tid >> 5] = a; s_sb[tid >> 5] = b; }
    __syncthreads();
    if (tid == 0) {
        float sum = 0.f, sq = 0.f;
        #pragma unroll
        for (int wdx = 0; wdx < 8; wdx++) { sum += s_sa[wdx]; sq += s_sb[wdx]; }
        float mean = sum * (1.f / 441.f);
        float var  = fmaxf(sq * (1.f / 441.f) - mean * mean, 0.f);
        s_mean = mean;
        s_inv  = 1.f / ((sqrtf(var) + EPSF) * 441.f);   // prep: exact is fine
    }
    __syncthreads();

    const float mean = s_mean, inv = s_inv;
    for (int idx = tid; idx < TH * NPAIR; idx += NTHREADS) {
        int i  = idx / NPAIR;
        int tt = idx % NPAIR;
        int j0 = 2 * tt;
        float e0 = (s_t[i * TH + j0] - mean) * inv;
        float e1 = (j0 + 1 < TH) ? (s_t[i * TH + j0 + 1] - mean) * inv : 0.f;
        float o0 = (j0 - 1 >= 0) ? (s_t[i * TH + j0 - 1] - mean) * inv : 0.f;
        ulonglong2 w;
        w.x = pack2(e0, e1);   // even-based outputs
        w.y = pack2(o0, e0);   // odd-based outputs
        g_wEO[plane * TH * NPAIR + idx] = w;
    }
}

// helper macros for the mainloop --------------------------------------------
#define LOAD_PIX(buf, rowptr) do { \
    _Pragma("unroll") \
    for (int _u = 0; _u < 9; _u++) { \
        ulonglong2 _q = *(const ulonglong2*)((rowptr) + coff[_u]); \
        (buf)[2 * _u] = _q.x; (buf)[2 * _u + 1] = _q.y; \
    } \
} while (0)

#define LOAD_W(wbuf, i) do { \
    _Pragma("unroll") \
    for (int _t = 0; _t < NPAIR; _t++) (wbuf)[_t] = s_wEO[(i) * NPAIR + _t]; \
} while (0)

// parity-split: even pass (b = w.x constant), then odd pass (b = w.y constant)
#define FMA_ROW(buf, wbuf) do { \
    _Pragma("unroll") \
    for (int _t = 0; _t < NPAIR; _t++) { \
        _Pragma("unroll") \
        for (int _g = 0; _g < 8; _g++) \
            FMA2V(acc[2 * _g], (buf)[_g + _t], (wbuf)[_t].x); \
        _Pragma("unroll") \
        for (int _g = 0; _g < 8; _g++) \
            FMA2V(acc[2 * _g + 1], (buf)[_g + _t], (wbuf)[_t].y); \
    } \
} while (0)

// tree-sum of V[0..20] (fixed rounding order, low latency)
__device__ __forceinline__ float tree21(const float* V) {
    float s01 = (V[0] + V[1]) + (V[2] + V[3]);
    float s02 = (V[4] + V[5]) + (V[6] + V[7]);
    float s03 = (V[8] + V[9]) + (V[10] + V[11]);
    float s04 = (V[12] + V[13]) + (V[14] + V[15]);
    float s05 = (V[16] + V[17]) + (V[18] + V[19]);
    return ((s01 + s02) + (s03 + s04)) + (s05 + V[20]);
}

// ---------------------------------------------------------------------------
// Pass 1: main NCC. Block = 128x32 tile; thread = 1 row x 16 consecutive cols.
// ---------------------------------------------------------------------------
__global__ __launch_bounds__(NTHREADS, 2)
void ncc_main(const float* __restrict__ inp, float* __restrict__ out) {
    extern __shared__ __align__(16) char dynsmem[];
    ulonglong2* s_wEO = (ulonglong2*)(dynsmem + OFF_W);
    char* s_in  = dynsmem + OFF_IN;
    char* s_v1  = dynsmem + OFF_V1;
    char* s_v2  = dynsmem + OFF_V2;

    const int plane = blockIdx.z;
    const int x0 = blockIdx.x * TILE_X;
    const int y0 = blockIdx.y * TILE_Y;
    const int tid = threadIdx.x;

    const float* pin = inp + (size_t)plane * (H * W);

    // Load input tile: 52 rows x 37 logical chunks, swizzled placement.
    for (int g = tid; g < SROWS * NCHUNK; g += NTHREADS) {
        int r = g / NCHUNK;
        int c = g - r * NCHUNK;              // logical 16B chunk
        int gy = y0 + r, gx = x0 + 4 * c;
        float4 v = make_float4(0.f, 0.f, 0.f, 0.f);
        if (gy < H && gx < W) v = *(const float4*)(pin + (size_t)gy * W + gx);
        *(float4*)(s_in + r * ROWB + swz(c) * 16) = v;
    }
    for (int idx = tid; idx < TH * NPAIR; idx += NTHREADS)
        s_wEO[idx] = g_wEO[plane * TH * NPAIR + idx];
    __syncthreads();

    const int xt = tid & 7;        // 16-output column group
    const int yt = tid >> 3;       // output row within tile

    // Precomputed swizzled byte offsets for this thread's 9 pixel chunks.
    int coff[9];
    #pragma unroll
    for (int u = 0; u < 9; u++) coff[u] = swz(4 * xt + u) * 16;

    ull acc[16];
    #pragma unroll
    for (int m = 0; m < 16; m++) acc[m] = 0ull;

    // ---- software-pipelined mainloop: 21 filter rows --------------------
    const char* base = s_in + yt * ROWB;
    ull p[18], q[18];
    ulonglong2 w[NPAIR];

    LOAD_PIX(p, base);                         // row 0
    #pragma unroll 1
    for (int i = 0; i < 20; i += 2) {
        LOAD_W(w, i);
        LOAD_PIX(q, base + (i + 1) * ROWB);    // prefetch row i+1
        FMA_ROW(p, w);                         // row i
        LOAD_W(w, i + 1);
        LOAD_PIX(p, base + (i + 2) * ROWB);    // prefetch row i+2 (<= 20)
        FMA_ROW(q, w);                         // row i+1
    }
    LOAD_W(w, 20);
    FMA_ROW(p, w);                             // row 20

    // Reduce packed accumulators now -> frees 16 regs before epilogue peak.
    float num[16];
    #pragma unroll
    for (int m = 0; m < 16; m++) num[m] = lo2(acc[m]) + hi2(acc[m]);

    // Vertical sliding box sums of x, x^2 (threads 0..147, one column each).
    // Reads swizzled input tile; writes compact linear V rows.
    if (tid < 148) {
        const int c = tid;
        const int colb = swz(c >> 2) * 16 + (c & 3) * 4;   // swizzled input off
        const int vb   = c * 4;                             // linear V offset
        float s1 = 0.f, s2 = 0.f;
        #pragma unroll
        for (int r = 0; r < TH; r++) {
            float v = *(const float*)(s_in + r * ROWB + colb);
            s1 += v; s2 += v * v;
        }
        *(float*)(s_v1 + vb) = s1;
        *(float*)(s_v2 + vb) = s2;
        for (int y = 1; y < TILE_Y; y++) {
            float va = *(const float*)(s_in + (y + 20) * ROWB + colb);
            float vr = *(const float*)(s_in + (y - 1) * ROWB + colb);
            s1 += va - vr;
            s2 += va * va - vr * vr;
            *(float*)(s_v1 + y * VROWB + vb) = s1;
            *(float*)(s_v2 + y * VROWB + vb) = s2;
        }
    }
    __syncthreads();

    // Epilogue: register-resident horizontal box sums + normalize + store.
    float h1[16], h2[16];
    {
        float V[36];
        #pragma unroll
        for (int u = 0; u < 9; u++) {
            float4 qv = *(const float4*)(s_v1 + yt * VROWB + (4 * xt + u) * 16);
            V[4*u] = qv.x; V[4*u+1] = qv.y; V[4*u+2] = qv.z; V[4*u+3] = qv.w;
        }
        float h = tree21(V);
        h1[0] = h;
        #pragma unroll
        for (int m = 1; m < 16; m++) { h += V[m + 20] - V[m - 1]; h1[m] = h; }
    }
    {
        float V[36];
        #pragma unroll
        for (int u = 0; u < 9; u++) {
            float4 qv = *(const float4*)(s_v2 + yt * VROWB + (4 * xt + u) * 16);
            V[4*u] = qv.x; V[4*u+1] = qv.y; V[4*u+2] = qv.z; V[4*u+3] = qv.w;
        }
        float h = tree21(V);
        h2[0] = h;
        #pragma unroll
        for (int m = 1; m < 16; m++) { h += V[m + 20] - V[m - 1]; h2[m] = h; }
    }

    const float inv441 = 1.f / 441.f;
    const int oy = y0 + yt;
    const int oxb = x0 + 16 * xt;
    if (oy < OH) {
        float* prow = out + (size_t)plane * (OH * OW) + (size_t)oy * OW;
        #pragma unroll
        for (int q4 = 0; q4 < 4; q4++) {
            int ox = oxb + 4 * q4;
            if (ox + 3 < OW) {                 // OW divisible by 4, ox 4-aligned
                float4 o;
                float* po = &o.x;
                #pragma unroll
                for (int e = 0; e < 4; e++) {
                    int m = 4 * q4 + e;
                    float mean = h1[m] * inv441;
                    float msq  = h2[m] * inv441;
                    float stdv = sqrt_approx(msq - mean * mean + EPSF);
                    po[e] = num[m] * rcp_approx(stdv + EPSF);
                }
                *(float4*)(prow + ox) = o;
            }
        }
    }
}

extern "C" void kernel_launch(void* const* d_in, const int* in_sizes, int n_in,
                              void* d_out, int out_size) {
    const float* inp  = (const float*)d_in[0];
    const float* tmpl = (const float*)d_in[1];
    if (n_in >= 2 && in_sizes[0] < in_sizes[1]) {
        const float* t = inp; inp = tmpl; tmpl = t;
    }
    cudaFuncSetAttribute(ncc_main, cudaFuncAttributeMaxDynamicSharedMemorySize,
                         SMEM_TOTAL);
    prep_template<<<PLANES, NTHREADS>>>(tmpl);
    dim3 grid((OW + TILE_X - 1) / TILE_X,   // 4
              (OH + TILE_Y - 1) / TILE_Y,   // 16
              PLANES);                      // 48
    ncc_main<<<grid, NTHREADS, SMEM_TOTAL>>>(inp, (float*)d_out);
}

// round 13
// speedup vs baseline: 1.0990x; 1.0990x over previous
#include <cuda_runtime.h>

// NCC: per-(b,c) 21x21 normalized cross-correlation, fp32.
// R13 = R10 (best, 254.1us) with EXACTLY two epilogue changes:
//   sqrtf -> sqrt.approx.f32, divide -> mul by rcp.approx.f32.
// Nothing else touched: R12 showed this kernel is register-allocation
// fragile (epilogue rework -> regs 110->128 -> 270us). Approx ops add zero
// live values, so allocation should be unchanged.

#define EPSF    1e-8f
#define TH      21
#define PLANES  48
#define H       512
#define W       512
#define OH      492
#define OW      492
#define NPAIR   11
#define TILE_X  128          // 8 x-threads * 16 outputs
#define TILE_Y  32           // 32 y-threads * 1 row
#define SROWS   (TILE_Y + 20)     // 52
#define NCHUNK  37                // 148 floats = 37 16B-chunks (logical)
#define ROWCH   40                // padded physical chunks per row
#define ROWB    (ROWCH * 16)      // 640 B row stride
#define NTHREADS 256

typedef unsigned long long ull;

// interleaved packed weight table: [plane][filter_row][pair] = (wE, wO)
__device__ ulonglong2 g_wEO[PLANES * TH * NPAIR];

__device__ __forceinline__ ull pack2(float a, float b) {
    ull r; asm("mov.b64 %0, {%1,%2};" : "=l"(r) : "f"(a), "f"(b)); return r;
}
__device__ __forceinline__ float lo2(ull v) { return __int_as_float((int)(v & 0xffffffffull)); }
__device__ __forceinline__ float hi2(ull v) { return __int_as_float((int)(v >> 32)); }

// volatile: keep issue order so consecutive FMA2s share the b-operand slot
#define FMA2V(acc, a, b) \
    asm volatile("fma.rn.f32x2 %0, %1, %2, %0;" : "+l"(acc) : "l"(a), "l"(b))

__device__ __forceinline__ float sqrt_approx(float x) {
    float r; asm("sqrt.approx.f32 %0, %1;" : "=f"(r) : "f"(x)); return r;
}
__device__ __forceinline__ float rcp_approx(float x) {
    float r; asm("rcp.approx.f32 %0, %1;" : "=f"(r) : "f"(x)); return r;
}

// XOR swizzle on 16B-chunk index (keeps chunks inside their 128B segment)
__device__ __forceinline__ int swz(int c) { return c ^ ((c >> 3) & 7); }

// smem layout (bytes)
#define OFF_W    0
#define SZ_W     (TH * NPAIR * 16)            // 3696
#define OFF_IN   3712                          // 16B aligned
#define SZ_IN    (SROWS * ROWB)                // 33280
#define OFF_V1   (OFF_IN + SZ_IN)              // 36992
#define SZ_V     (TILE_Y * ROWB)               // 20480
#define OFF_V2   (OFF_V1 + SZ_V)               // 57472
#define SMEM_TOTAL (OFF_V2 + SZ_V)             // 77952

// ---------------------------------------------------------------------------
// Pass 0: normalize template planes, build interleaved packed weight table.
// ---------------------------------------------------------------------------
__global__ void prep_template(const float* __restrict__ tmpl) {
    const int plane = blockIdx.x;
    const float* t = tmpl + plane * (TH * TH);

    __shared__ float s_t[TH * TH];
    __shared__ float s_sa[8], s_sb[8];
    __shared__ float s_mean, s_inv;

    int tid = threadIdx.x;
    float a = 0.f, b = 0.f;
    for (int i = tid; i < TH * TH; i += NTHREADS) {
        float v = t[i];
        s_t[i] = v;
        a += v; b += v * v;
    }
    #pragma unroll
    for (int o = 16; o; o >>= 1) {
        a += __shfl_xor_sync(0xffffffffu, a, o);
        b += __shfl_xor_sync(0xffffffffu, b, o);
    }
    if ((tid & 31) == 0) { s_sa[tid >> 5] = a; s_sb[tid >> 5] = b; }
    __syncthreads();
    if (tid == 0) {
        float sum = 0.f, sq = 0.f;
        #pragma unroll
        for (int wdx = 0; wdx < 8; wdx++) { sum += s_sa[wdx]; sq += s_sb[wdx]; }
        float mean = sum * (1.f / 441.f);
        float var  = fmaxf(sq * (1.f / 441.f) - mean * mean, 0.f);
        s_mean = mean;
        s_inv  = 1.f / ((sqrtf(var) + EPSF) * 441.f);   // prep: exact (once)
    }
    __syncthreads();

    const float mean = s_mean, inv = s_inv;
    for (int idx = tid; idx < TH * NPAIR; idx += NTHREADS) {
        int i  = idx / NPAIR;
        int tt = idx % NPAIR;
        int j0 = 2 * tt;
        float e0 = (s_t[i * TH + j0] - mean) * inv;
        float e1 = (j0 + 1 < TH) ? (s_t[i * TH + j0 + 1] - mean) * inv : 0.f;
        float o0 = (j0 - 1 >= 0) ? (s_t[i * TH + j0 - 1] - mean) * inv : 0.f;
        ulonglong2 w;
        w.x = pack2(e0, e1);   // even-based outputs
        w.y = pack2(o0, e0);   // odd-based outputs
        g_wEO[plane * TH * NPAIR + idx] = w;
    }
}

// helper macros for the mainloop --------------------------------------------
#define LOAD_PIX(buf, rowptr) do { \
    _Pragma("unroll") \
    for (int _u = 0; _u < 9; _u++) { \
        ulonglong2 _q = *(const ulonglong2*)((rowptr) + coff[_u]); \
        (buf)[2 * _u] = _q.x; (buf)[2 * _u + 1] = _q.y; \
    } \
} while (0)

#define LOAD_W(wbuf, i) do { \
    _Pragma("unroll") \
    for (int _t = 0; _t < NPAIR; _t++) (wbuf)[_t] = s_wEO[(i) * NPAIR + _t]; \
} while (0)

// parity-split: even pass (b = w.x constant), then odd pass (b = w.y constant)
#define FMA_ROW(buf, wbuf) do { \
    _Pragma("unroll") \
    for (int _t = 0; _t < NPAIR; _t++) { \
        _Pragma("unroll") \
        for (int _g = 0; _g < 8; _g++) \
            FMA2V(acc[2 * _g], (buf)[_g + _t], (wbuf)[_t].x); \
        _Pragma("unroll") \
        for (int _g = 0; _g < 8; _g++) \
            FMA2V(acc[2 * _g + 1], (buf)[_g + _t], (wbuf)[_t].y); \
    } \
} while (0)

// ---------------------------------------------------------------------------
// Pass 1: main NCC. Block = 128x32 tile; thread = 1 row x 16 consecutive cols.
// ---------------------------------------------------------------------------
__global__ __launch_bounds__(NTHREADS, 2)
void ncc_main(const float* __restrict__ inp, float* __restrict__ out) {
    extern __shared__ __align__(16) char dynsmem[];
    ulonglong2* s_wEO = (ulonglong2*)(dynsmem + OFF_W);
    char* s_in  = dynsmem + OFF_IN;
    char* s_v1  = dynsmem + OFF_V1;
    char* s_v2  = dynsmem + OFF_V2;

    const int plane = blockIdx.z;
    const int x0 = blockIdx.x * TILE_X;
    const int y0 = blockIdx.y * TILE_Y;
    const int tid = threadIdx.x;

    const float* pin = inp + (size_t)plane * (H * W);

    // Load input tile: 52 rows x 37 logical chunks, swizzled placement.
    for (int g = tid; g < SROWS * NCHUNK; g += NTHREADS) {
        int r = g / NCHUNK;
        int c = g - r * NCHUNK;              // logical 16B chunk
        int gy = y0 + r, gx = x0 + 4 * c;
        float4 v = make_float4(0.f, 0.f, 0.f, 0.f);
        if (gy < H && gx < W) v = *(const float4*)(pin + (size_t)gy * W + gx);
        *(float4*)(s_in + r * ROWB + swz(c) * 16) = v;
    }
    for (int idx = tid; idx < TH * NPAIR; idx += NTHREADS)
        s_wEO[idx] = g_wEO[plane * TH * NPAIR + idx];
    __syncthreads();

    const int xt = tid & 7;        // 16-output column group
    const int yt = tid >> 3;       // output row within tile

    // Precomputed swizzled byte offsets for this thread's 9 pixel chunks.
    int coff[9];
    #pragma unroll
    for (int u = 0; u < 9; u++) coff[u] = swz(4 * xt + u) * 16;

    ull acc[16];
    #pragma unroll
    for (int m = 0; m < 16; m++) acc[m] = 0ull;

    // ---- software-pipelined mainloop: 21 filter rows --------------------
    const char* base = s_in + yt * ROWB;
    ull p[18], q[18];
    ulonglong2 w[NPAIR];

    LOAD_PIX(p, base);                         // row 0
    #pragma unroll 1
    for (int i = 0; i < 20; i += 2) {
        LOAD_W(w, i);
        LOAD_PIX(q, base + (i + 1) * ROWB);    // prefetch row i+1
        FMA_ROW(p, w);                         // row i
        LOAD_W(w, i + 1);
        LOAD_PIX(p, base + (i + 2) * ROWB);    // prefetch row i+2 (<= 20)
        FMA_ROW(q, w);                         // row i+1
    }
    LOAD_W(w, 20);
    FMA_ROW(p, w);                             // row 20

    // Vertical sliding box sums of x, x^2 (threads 0..147, one column each),
    // written swizzled so the epilogue can vector-load them.
    if (tid < 148) {
        const int c = tid;
        const int colb = swz(c >> 2) * 16 + (c & 3) * 4;   // swizzled byte off
        float s1 = 0.f, s2 = 0.f;
        #pragma unroll
        for (int r = 0; r < TH; r++) {
            float v = *(const float*)(s_in + r * ROWB + colb);
            s1 += v; s2 += v * v;
        }
        *(float*)(s_v1 + colb) = s1;
        *(float*)(s_v2 + colb) = s2;
        for (int y = 1; y < TILE_Y; y++) {
            float va = *(const float*)(s_in + (y + 20) * ROWB + colb);
            float vr = *(const float*)(s_in + (y - 1) * ROWB + colb);
            s1 += va - vr;
            s2 += va * va - vr * vr;
            *(float*)(s_v1 + y * ROWB + colb) = s1;
            *(float*)(s_v2 + y * ROWB + colb) = s2;
        }
    }
    __syncthreads();

    // Epilogue: reduce packed accumulators, register-resident horizontal sums.
    float num[16];
    #pragma unroll
    for (int m = 0; m < 16; m++) num[m] = lo2(acc[m]) + hi2(acc[m]);

    float h1[16], h2[16];
    {
        float V[36];
        #pragma unroll
        for (int u = 0; u < 9; u++) {
            float4 qv = *(const float4*)(s_v1 + yt * ROWB + coff[u]);
            V[4*u] = qv.x; V[4*u+1] = qv.y; V[4*u+2] = qv.z; V[4*u+3] = qv.w;
        }
        float h = 0.f;
        #pragma unroll
        for (int k = 0; k < TH; k++) h += V[k];
        h1[0] = h;
        #pragma unroll
        for (int m = 1; m < 16; m++) { h += V[m + 20] - V[m - 1]; h1[m] = h; }
    }
    {
        float V[36];
        #pragma unroll
        for (int u = 0; u < 9; u++) {
            float4 qv = *(const float4*)(s_v2 + yt * ROWB + coff[u]);
            V[4*u] = qv.x; V[4*u+1] = qv.y; V[4*u+2] = qv.z; V[4*u+3] = qv.w;
        }
        float h = 0.f;
        #pragma unroll
        for (int k = 0; k < TH; k++) h += V[k];
        h2[0] = h;
        #pragma unroll
        for (int m = 1; m < 16; m++) { h += V[m + 20] - V[m - 1]; h2[m] = h; }
    }

    const float inv441 = 1.f / 441.f;
    const int oy = y0 + yt;
    const int oxb = x0 + 16 * xt;
    if (oy < OH) {
        float* prow = out + (size_t)plane * (OH * OW) + (size_t)oy * OW;
        #pragma unroll
        for (int q4 = 0; q4 < 4; q4++) {
            int ox = oxb + 4 * q4;
            if (ox + 3 < OW) {                 // OW divisible by 4, ox 4-aligned
                float4 o;
                float* po = &o.x;
                #pragma unroll
                for (int e = 0; e < 4; e++) {
                    int m = 4 * q4 + e;
                    float mean = h1[m] * inv441;
                    float msq  = h2[m] * inv441;
                    float stdv = sqrt_approx(msq - mean * mean + EPSF);
                    po[e] = num[m] * rcp_approx(stdv + EPSF);
                }
                *(float4*)(prow + ox) = o;
            }
        }
    }
}

extern "C" void kernel_launch(void* const* d_in, const int* in_sizes, int n_in,
                              void* d_out, int out_size) {
    const float* inp  = (const float*)d_in[0];
    const float* tmpl = (const float*)d_in[1];
    if (n_in >= 2 && in_sizes[0] < in_sizes[1]) {
        const float* t = inp; inp = tmpl; tmpl = t;
    }
    cudaFuncSetAttribute(ncc_main, cudaFuncAttributeMaxDynamicSharedMemorySize,
                         SMEM_TOTAL);
    prep_template<<<PLANES, NTHREADS>>>(tmpl);
    dim3 grid((OW + TILE_X - 1) / TILE_X,   // 4
              (OH + TILE_Y - 1) / TILE_Y,   // 16
              PLANES);                      // 48
    ncc_main<<<grid, NTHREADS, SMEM_TOTAL>>>(inp, (float*)d_out);
}